// round 8
// baseline (speedup 1.0000x reference)
#include <cuda_runtime.h>
#include <cuda_fp16.h>
#include <mma.h>
#include <cstdint>

using namespace nvcuda;

// ----------------------------------------------------------------------------
// out[64,14336](fp32) = (x[64,4096]*xs) @ (w[14336,4096]*ws)^T
// R7 theory: harness promotes dtypes it doesn't list: int8 -> int32,
// float16 -> float32. All prior rounds read int8 garbage from int32 buffers
// and wrote fp16 into an fp32 buffer (half of it stayed poisoned -> identical
// poison-dominated rel_err across five different kernels).
// This round: int32 inputs, fp32 output, wmma HMMA core (exact integer math),
// static shared memory, single plain launch.
// CTA: 128 features x 64 tokens; grid 112; 8 warps each own 16 features.
// ----------------------------------------------------------------------------

#define M_TOK   64
#define KDIM    4096
#define NOUT    14336
#define TILE_N  128
#define KC      64                       // K elements per chunk
#define ITERS   (KDIM / KC)              // 64
#define WSTRIDE 72                       // halves per smem row (64 + 8 pad)
#define OUT_ELEMS ((long)M_TOK * NOUT)   // 917504

// zero-fill whole output buffer (tail-safe; also a run/no-run diagnostic)
__global__ void fill_kernel(float* out, long n) {
    long i = (long)blockIdx.x * blockDim.x + threadIdx.x;
    if (i < n) out[i] = 0.0f;
}

__global__ __launch_bounds__(256) void Model_89704686944640_kernel(
    const int* __restrict__ w, const int* __restrict__ x,
    const float* __restrict__ s0, const float* __restrict__ s1,
    float* __restrict__ out) {
    __shared__ __half wsm[TILE_N][WSTRIDE];   // 18432 B
    __shared__ __half xsm[M_TOK][WSTRIDE];    //  9216 B

    const int tid = threadIdx.x;
    const int wid = tid >> 5;
    const int tile = blockIdx.x;
    const long wbase = (long)tile * TILE_N * KDIM;

    wmma::fragment<wmma::accumulator, 16, 16, 16, float> c[4];
#pragma unroll
    for (int mt = 0; mt < 4; mt++) wmma::fill_fragment(c[mt], 0.0f);

    // Per iter: W = 128 rows x 64 ints = 2048 uint4 chunks -> 8/thread
    //           X =  64 rows x 64 ints = 1024 uint4 chunks -> 4/thread
    // chunk idx -> row = idx>>4, col4 = (idx&15)*4 (4 ints per uint4)
    uint4 wr[8], xr[4];
    {
#pragma unroll
        for (int r = 0; r < 8; r++) {
            int idx = tid + r * 256;
            int row = idx >> 4, c4 = (idx & 15) * 4;
            wr[r] = *reinterpret_cast<const uint4*>(w + wbase + (long)row * KDIM + c4);
        }
#pragma unroll
        for (int r = 0; r < 4; r++) {
            int idx = tid + r * 256;
            int row = idx >> 4, c4 = (idx & 15) * 4;
            xr[r] = *reinterpret_cast<const uint4*>(x + (long)row * KDIM + c4);
        }
    }

    for (int it = 0; it < ITERS; it++) {
        __syncthreads();   // previous chunk's compute done; smem reusable
#pragma unroll
        for (int r = 0; r < 8; r++) {
            int idx = tid + r * 256;
            int row = idx >> 4, c4 = (idx & 15) * 4;
            __half2 p0 = __halves2half2(__int2half_rn((int)wr[r].x),
                                        __int2half_rn((int)wr[r].y));
            __half2 p1 = __halves2half2(__int2half_rn((int)wr[r].z),
                                        __int2half_rn((int)wr[r].w));
            *reinterpret_cast<__half2*>(&wsm[row][c4])     = p0;
            *reinterpret_cast<__half2*>(&wsm[row][c4 + 2]) = p1;
        }
#pragma unroll
        for (int r = 0; r < 4; r++) {
            int idx = tid + r * 256;
            int row = idx >> 4, c4 = (idx & 15) * 4;
            __half2 p0 = __halves2half2(__int2half_rn((int)xr[r].x),
                                        __int2half_rn((int)xr[r].y));
            __half2 p1 = __halves2half2(__int2half_rn((int)xr[r].z),
                                        __int2half_rn((int)xr[r].w));
            *reinterpret_cast<__half2*>(&xsm[row][c4])     = p0;
            *reinterpret_cast<__half2*>(&xsm[row][c4 + 2]) = p1;
        }
        __syncthreads();   // smem tile ready

        if (it + 1 < ITERS) {  // prefetch next chunk into registers
            const int koff = (it + 1) * KC;
#pragma unroll
            for (int r = 0; r < 8; r++) {
                int idx = tid + r * 256;
                int row = idx >> 4, c4 = (idx & 15) * 4;
                wr[r] = *reinterpret_cast<const uint4*>(
                    w + wbase + (long)row * KDIM + koff + c4);
            }
#pragma unroll
            for (int r = 0; r < 4; r++) {
                int idx = tid + r * 256;
                int row = idx >> 4, c4 = (idx & 15) * 4;
                xr[r] = *reinterpret_cast<const uint4*>(
                    x + (long)row * KDIM + koff + c4);
            }
        }

        // compute: A = X tile (row_major, m=token,k), B = W tile (col_major, k, n=feature)
#pragma unroll
        for (int ks = 0; ks < 4; ks++) {
            wmma::fragment<wmma::matrix_b, 16, 16, 16, __half, wmma::col_major> bfrag;
            wmma::load_matrix_sync(bfrag, &wsm[wid * 16][ks * 16], WSTRIDE);
#pragma unroll
            for (int mt = 0; mt < 4; mt++) {
                wmma::fragment<wmma::matrix_a, 16, 16, 16, __half, wmma::row_major> afrag;
                wmma::load_matrix_sync(afrag, &xsm[mt * 16][ks * 16], WSTRIDE);
                wmma::mma_sync(c[mt], afrag, bfrag, c[mt]);
            }
        }
    }

    // ---- epilogue: scale in-fragment, store fp32 direct to gmem ----
    float sc = s0 ? s0[0] : 1.0f;
    if (s1) sc *= s1[0];
#pragma unroll
    for (int mt = 0; mt < 4; mt++) {
#pragma unroll
        for (int i = 0; i < c[mt].num_elements; i++) c[mt].x[i] *= sc;
        // rows = tokens mt*16.., cols = features tile*128 + wid*16..
        wmma::store_matrix_sync(out + (long)(mt * 16) * NOUT + (long)tile * TILE_N + wid * 16,
                                c[mt], NOUT, wmma::mem_row_major);
    }
}

extern "C" void kernel_launch(void* const* d_in, const int* in_sizes, int n_in,
                              void* d_out, int out_size) {
    // Resolve inputs by SIZE (element counts are dtype-agnostic), with
    // positional fallback. Under the promotion theory the int8 arrays arrive
    // as int32 buffers and the fp16 output buffer is fp32.
    const int* w_q = nullptr;
    const int* x_q = nullptr;
    const float* s0 = nullptr;
    const float* s1 = nullptr;
    for (int i = 0; i < n_in; i++) {
        long n = in_sizes[i];
        if (n == (long)NOUT * KDIM) w_q = (const int*)d_in[i];
        else if (n == (long)M_TOK * KDIM) x_q = (const int*)d_in[i];
        else if (n <= 1) { if (!s0) s0 = (const float*)d_in[i]; else if (!s1) s1 = (const float*)d_in[i]; }
    }
    if (!x_q && n_in > 0) x_q = (const int*)d_in[0];
    if (!s0 && n_in > 1) s0 = (const float*)d_in[1];
    if (!w_q && n_in > 2) w_q = (const int*)d_in[2];
    if (!s1 && n_in > 3) s1 = (const float*)d_in[3];
    float* out = (float*)d_out;

    // 1) zero the whole declared output (tail-safe + run diagnostic)
    long n = (long)out_size;
    fill_kernel<<<(int)((n + 255) / 256), 256>>>(out, n);

    // 2) GEMM: static smem only, plain launch
    if (w_q && x_q)
        Model_89704686944640_kernel<<<NOUT / TILE_N, 256>>>(w_q, x_q, s0, s1, out);
}